// round 12
// baseline (speedup 1.0000x reference)
#include <cuda_runtime.h>
#include <cstdint>

#define DIN  128
#define DOUT 128
#define EDIM 16
#define MAXN 50176
#define MAXE 819200
#define BN_EPS 1e-5f
#define SCAN_BLK 512
#define NWARPS (SCAN_BLK / 32)   // 16
#define MAXB1 128                // >= ceil(MAXN/SCAN_BLK) = 98

// ---------------- device scratch (static; zero-initialized at load) ---------
// Invariant: g_cnt, g_sum, g_sumsq, g_ea are ZERO at the start of every
// kernel_launch run (statics zero-init; each run re-zeroes after use).
__device__ float g_x  [MAXN * DOUT];   // feats @ W_rel^T + b_rel
__device__ float g_res[MAXN * DOUT];   // relu(feats @ W_res^T + b_res)
__device__ float g_h  [MAXN * DOUT];   // pre-BN activations
__device__ float g_ea [MAXN * EDIM];   // scatter-add of edge_attr per dst
__device__ int   g_cnt[MAXN];          // per-dst degree (histogram)
__device__ int   g_off[MAXN + 1];      // CSR offsets
__device__ int   g_cur[MAXN];          // placement cursors
__device__ int   g_csr_src[MAXE];      // src node per CSR slot
__device__ int   g_bsum[MAXB1];        // scan phase-1 block sums
__device__ float g_sum  [DOUT];
__device__ float g_sumsq[DOUT];
__device__ float g_scale[DOUT];
__device__ float g_shift[DOUT];
__device__ int   g_is64;               // edge_index dtype flag

__device__ __forceinline__ void red_add_v4(float* p, float4 v) {
    asm volatile("red.global.add.v4.f32 [%0], {%1,%2,%3,%4};"
                 :: "l"(p), "f"(v.x), "f"(v.y), "f"(v.z), "f"(v.w)
                 : "memory");
}

__device__ __forceinline__ uint32_t cvt_tf32(float a) {
    uint32_t r;
    asm("cvt.rna.tf32.f32 %0, %1;" : "=r"(r) : "f"(a));
    return r;
}

__device__ __forceinline__ void mma_tf32(float* d, const uint32_t* a, const uint32_t* b) {
    asm volatile(
        "mma.sync.aligned.m16n8k8.row.col.f32.tf32.tf32.f32 "
        "{%0,%1,%2,%3}, {%4,%5,%6,%7}, {%8,%9}, {%0,%1,%2,%3};"
        : "+f"(d[0]), "+f"(d[1]), "+f"(d[2]), "+f"(d[3])
        : "r"(a[0]), "r"(a[1]), "r"(a[2]), "r"(a[3]), "r"(b[0]), "r"(b[1]));
}

// ---------------- K_hist: per-block dtype detect + histogram over dst --------
__global__ __launch_bounds__(256)
void k_hist(const void* __restrict__ ei_raw, int E)
{
    __shared__ int blk_nz;
    const unsigned int* w = (const unsigned int*)ei_raw;
    if (threadIdx.x == 0) blk_nz = 0;
    __syncthreads();
    if (w[2 * threadIdx.x + 1] != 0u) atomicOr(&blk_nz, 1);
    __syncthreads();
    const int is64 = blk_nz ? 0 : 1;
    if (blockIdx.x == 0 && threadIdx.x == 0) g_is64 = is64;

    int e = blockIdx.x * blockDim.x + threadIdx.x;
    if (e >= E) return;
    int d = is64 ? (int)((const long long*)ei_raw)[E + e]
                 : ((const int*)ei_raw)[E + e];
    atomicAdd(&g_cnt[d], 1);
}

// ---------------- K_scan1: per-block sums -------------------------------------
__global__ __launch_bounds__(SCAN_BLK)
void k_scan1(int N)
{
    __shared__ int wsum[NWARPS];
    int i = blockIdx.x * SCAN_BLK + threadIdx.x;
    int wid = threadIdx.x >> 5, lane = threadIdx.x & 31;
    int v = (i < N) ? g_cnt[i] : 0;
    #pragma unroll
    for (int o = 16; o > 0; o >>= 1) v += __shfl_down_sync(0xffffffffu, v, o);
    if (lane == 0) wsum[wid] = v;
    __syncthreads();
    if (wid == 0) {
        int s = (lane < NWARPS) ? wsum[lane] : 0;
        #pragma unroll
        for (int o = 16; o > 0; o >>= 1) s += __shfl_down_sync(0xffffffffu, s, o);
        if (lane == 0) g_bsum[blockIdx.x] = s;
    }
}

// ---------------- K_scan3m: block-local scan + inline cross-block offset -----
__global__ __launch_bounds__(SCAN_BLK)
void k_scan3m(int nb, int N)
{
    __shared__ int wsum[NWARPS];
    __shared__ int s_boff, s_total;
    int i = blockIdx.x * SCAN_BLK + threadIdx.x;
    int wid = threadIdx.x >> 5, lane = threadIdx.x & 31;

    if (wid == 0) {
        int pre = 0, tot = 0;
        for (int b = lane; b < nb; b += 32) {
            int s = g_bsum[b];
            tot += s;
            if (b < (int)blockIdx.x) pre += s;
        }
        #pragma unroll
        for (int o = 16; o > 0; o >>= 1) {
            pre += __shfl_down_sync(0xffffffffu, pre, o);
            tot += __shfl_down_sync(0xffffffffu, tot, o);
        }
        if (lane == 0) { s_boff = pre; s_total = tot; }
    }

    int v = (i < N) ? g_cnt[i] : 0;
    int x = v;
    #pragma unroll
    for (int o = 1; o < 32; o <<= 1) {
        int y = __shfl_up_sync(0xffffffffu, x, o);
        if (lane >= o) x += y;
    }
    if (lane == 31) wsum[wid] = x;
    __syncthreads();
    if (wid == 0) {
        int s = (lane < NWARPS) ? wsum[lane] : 0;
        #pragma unroll
        for (int o = 1; o < 32; o <<= 1) {
            int y = __shfl_up_sync(0xffffffffu, s, o);
            if (lane >= o) s += y;
        }
        if (lane < NWARPS) wsum[lane] = s;
    }
    __syncthreads();
    int woff = (wid > 0) ? wsum[wid - 1] : 0;
    int excl = x - v + woff + s_boff;
    if (i < N) {
        g_off[i] = excl;
        g_cur[i] = excl;
        g_cnt[i] = 0;                      // restore zero-invariant
    }
    if (blockIdx.x == nb - 1 && threadIdx.x == 0) g_off[N] = s_total;
}

// ---------------- K_place: CSR placement + scatter edge_attr sums ------------
__global__ __launch_bounds__(256)
void k_place(const void* __restrict__ ei_raw, const float* __restrict__ eattr, int E)
{
    int e = blockIdx.x * blockDim.x + threadIdx.x;
    if (e >= E) return;
    int s, d;
    if (g_is64) {
        const long long* p = (const long long*)ei_raw;
        s = (int)p[e]; d = (int)p[E + e];
    } else {
        const int* p = (const int*)ei_raw;
        s = p[e]; d = p[E + e];
    }
    int pos = atomicAdd(&g_cur[d], 1);
    g_csr_src[pos] = s;

    const float4* a4 = (const float4*)&eattr[(size_t)e * EDIM];
    float* dst = &g_ea[(size_t)d * EDIM];
    red_add_v4(dst + 0,  a4[0]);
    red_add_v4(dst + 4,  a4[1]);
    red_add_v4(dst + 8,  a4[2]);
    red_add_v4(dst + 12, a4[3]);
}

// ---------------- K1: tf32 tensor-core node GEMMs (R9 version, best measured)
#define K1_KT       64
#define K1_PITCH    68
#define K1_AS_FL    (128 * K1_PITCH)        // 8704 floats
#define K1_BF_FL    (8 * 8 * 32 * 4)        // 8192 floats
#define K1_SMEM     ((K1_AS_FL + K1_BF_FL) * 4)   // 67584 bytes

__global__ __launch_bounds__(256)
void k1_gemm_tf32(const float* __restrict__ feats,
                  const float* __restrict__ Wrel, const float* __restrict__ brel,
                  const float* __restrict__ Wres, const float* __restrict__ bres,
                  int N)
{
    extern __shared__ float smem[];
    float* As = smem;              // [128][68] fp32
    float* Bf = smem + K1_AS_FL;   // frag-major B hi/lo

    const int tid   = threadIdx.x;
    const int m0    = blockIdx.x * 128;
    const int mat   = blockIdx.y >> 1;
    const int nhalf = blockIdx.y & 1;

    const float* Wsel = (mat == 0) ? Wrel : Wres;
    const float* bsel = (mat == 0) ? brel : bres;
    const int nbase = nhalf * 64;

    const int warp = tid >> 5, lane = tid & 31;
    const int g = lane >> 2, tig = lane & 3;
    const int mwarp = warp >> 1;
    const int nwarp = warp & 1;
    const int am0 = mwarp * 32;

    float d[2][4][4];
    #pragma unroll
    for (int mi = 0; mi < 2; mi++)
        #pragma unroll
        for (int ns = 0; ns < 4; ns++)
            #pragma unroll
            for (int q = 0; q < 4; q++) d[mi][ns][q] = 0.f;

    for (int kt = 0; kt < DIN / K1_KT; kt++) {
        const int koff = kt * K1_KT;
        __syncthreads();
        for (int idx = tid; idx < 128 * 16; idx += 256) {
            int row = idx >> 4, c4 = idx & 15;
            int node = m0 + row;
            float4 v = (node < N)
                ? *(const float4*)&feats[(size_t)node * DIN + koff + c4 * 4]
                : make_float4(0.f, 0.f, 0.f, 0.f);
            *(float4*)&As[row * K1_PITCH + c4 * 4] = v;
        }
        for (int idx = tid; idx < 8 * 8 * 32; idx += 256) {
            int ks = idx >> 8;
            int ns = (idx >> 5) & 7;
            int ln = idx & 31;
            int gg = ln >> 2, tg = ln & 3;
            int nrow = nbase + ns * 8 + gg;
            const float* wr = &Wsel[(size_t)nrow * DIN + koff + ks * 8 + tg];
            float w0 = wr[0], w1 = wr[4];
            uint32_t h0 = cvt_tf32(w0);
            uint32_t h1 = cvt_tf32(w1);
            uint32_t l0 = cvt_tf32(w0 - __uint_as_float(h0));
            uint32_t l1 = cvt_tf32(w1 - __uint_as_float(h1));
            *(float4*)&Bf[(size_t)idx * 4] =
                make_float4(__uint_as_float(h0), __uint_as_float(h1),
                            __uint_as_float(l0), __uint_as_float(l1));
        }
        __syncthreads();

        #pragma unroll
        for (int ks = 0; ks < K1_KT / 8; ks++) {
            const int k0 = ks * 8;
            float af[8];
            #pragma unroll
            for (int mi = 0; mi < 2; mi++) {
                int r0 = am0 + mi * 16 + g;
                af[mi*4+0] = As[r0 * K1_PITCH + k0 + tig];
                af[mi*4+1] = As[(r0 + 8) * K1_PITCH + k0 + tig];
                af[mi*4+2] = As[r0 * K1_PITCH + k0 + tig + 4];
                af[mi*4+3] = As[(r0 + 8) * K1_PITCH + k0 + tig + 4];
            }
            uint32_t ah[8], al[8];
            #pragma unroll
            for (int q = 0; q < 8; q++) {
                ah[q] = cvt_tf32(af[q]);
                al[q] = cvt_tf32(af[q] - __uint_as_float(ah[q]));
            }
            #pragma unroll
            for (int nsl = 0; nsl < 4; nsl++) {
                const int nsg = nwarp * 4 + nsl;
                float4 b = *(const float4*)&Bf[((ks * 8 + nsg) * 32 + lane) * 4];
                uint32_t bh[2] = {__float_as_uint(b.x), __float_as_uint(b.y)};
                uint32_t bl[2] = {__float_as_uint(b.z), __float_as_uint(b.w)};
                #pragma unroll
                for (int mi = 0; mi < 2; mi++) {
                    mma_tf32(d[mi][nsl], ah + 4*mi, bh);
                    mma_tf32(d[mi][nsl], al + 4*mi, bh);
                    mma_tf32(d[mi][nsl], ah + 4*mi, bl);
                }
            }
        }
    }

    float* out = (mat == 0) ? g_x : g_res;
    #pragma unroll
    for (int mi = 0; mi < 2; mi++) {
        const int rA = m0 + am0 + mi * 16 + g;
        #pragma unroll
        for (int nsl = 0; nsl < 4; nsl++) {
            const int col = nbase + (nwarp * 4 + nsl) * 8 + tig * 2;
            float b0 = bsel[col], b1 = bsel[col + 1];
            float v0 = d[mi][nsl][0] + b0, v1 = d[mi][nsl][1] + b1;
            float v2 = d[mi][nsl][2] + b0, v3 = d[mi][nsl][3] + b1;
            if (mat == 1) {
                v0 = fmaxf(v0, 0.f); v1 = fmaxf(v1, 0.f);
                v2 = fmaxf(v2, 0.f); v3 = fmaxf(v3, 0.f);
            }
            if (rA < N)
                *(float2*)&out[(size_t)rA * DOUT + col] = make_float2(v0, v1);
            if (rA + 8 < N)
                *(float2*)&out[(size_t)(rA + 8) * DOUT + col] = make_float2(v2, v3);
        }
    }
}

// ---------------- K_pull: coalesced-index gather + combine + BN partials -----
// One warp per node. A node's CSR indices are CONTIGUOUS: one coalesced load
// g_csr_src[base+lane] fetches up to 32 indices; shfl broadcasts each, so the
// 512B row gathers issue back-to-back with no dependent index loads between.
__global__ __launch_bounds__(256)
void k_pull(const float* __restrict__ We, const float* __restrict__ be, int N)
{
    __shared__ float s_sum[128];
    __shared__ float s_sq[128];
    int tid = threadIdx.x;
    if (tid < 128) { s_sum[tid] = 0.f; s_sq[tid] = 0.f; }
    __syncthreads();

    int warp = tid >> 5, lane = tid & 31;
    int n = blockIdx.x * 8 + warp;

    if (n < N) {
        const int j0 = g_off[n], j1 = g_off[n + 1];
        const int c0 = lane * 4;

        float4 acc = make_float4(0.f, 0.f, 0.f, 0.f);

        for (int base = j0; base < j1; base += 32) {
            // one coalesced index load for up to 32 edges (overread harmless:
            // bounded by MAXE >= E + 31)
            int myidx = g_csr_src[base + lane];
            int cnt = j1 - base; if (cnt > 32) cnt = 32;
            int t = 0;
            for (; t + 3 < cnt; t += 4) {
                int s0 = __shfl_sync(0xffffffffu, myidx, t);
                int s1 = __shfl_sync(0xffffffffu, myidx, t + 1);
                int s2 = __shfl_sync(0xffffffffu, myidx, t + 2);
                int s3 = __shfl_sync(0xffffffffu, myidx, t + 3);
                float4 x0 = *(const float4*)&g_x[(size_t)s0 * DOUT + c0];
                float4 x1 = *(const float4*)&g_x[(size_t)s1 * DOUT + c0];
                float4 x2 = *(const float4*)&g_x[(size_t)s2 * DOUT + c0];
                float4 x3 = *(const float4*)&g_x[(size_t)s3 * DOUT + c0];
                acc.x += (x0.x + x1.x) + (x2.x + x3.x);
                acc.y += (x0.y + x1.y) + (x2.y + x3.y);
                acc.z += (x0.z + x1.z) + (x2.z + x3.z);
                acc.w += (x0.w + x1.w) + (x2.w + x3.w);
            }
            for (; t < cnt; t++) {
                int s0 = __shfl_sync(0xffffffffu, myidx, t);
                float4 x0 = *(const float4*)&g_x[(size_t)s0 * DOUT + c0];
                acc.x += x0.x; acc.y += x0.y; acc.z += x0.z; acc.w += x0.w;
            }
        }

        // per-dst summed edge_attr -> broadcast; then reset for next run
        float ea = 0.f;
        if (lane < EDIM) {
            ea = g_ea[(size_t)n * EDIM + lane];
            g_ea[(size_t)n * EDIM + lane] = 0.f;
        }
        float eav[EDIM];
        #pragma unroll
        for (int q = 0; q < EDIM; q++) eav[q] = __shfl_sync(0xffffffffu, ea, q);

        const float deg = (float)(j1 - j0);
        float4 b = *(const float4*)&be[c0];
        float4 elin = make_float4(b.x * deg, b.y * deg, b.z * deg, b.w * deg);

        const float4* W4 = (const float4*)We;
        #pragma unroll
        for (int q4 = 0; q4 < 4; q4++) {
            float4 w0 = W4[(c0 + 0) * 4 + q4];
            float4 w1 = W4[(c0 + 1) * 4 + q4];
            float4 w2 = W4[(c0 + 2) * 4 + q4];
            float4 w3 = W4[(c0 + 3) * 4 + q4];
            float e0v = eav[q4 * 4 + 0], e1v = eav[q4 * 4 + 1];
            float e2v = eav[q4 * 4 + 2], e3v = eav[q4 * 4 + 3];
            elin.x += w0.x * e0v + w0.y * e1v + w0.z * e2v + w0.w * e3v;
            elin.y += w1.x * e0v + w1.y * e1v + w1.z * e2v + w1.w * e3v;
            elin.z += w2.x * e0v + w2.y * e1v + w2.z * e2v + w2.w * e3v;
            elin.w += w3.x * e0v + w3.y * e1v + w3.z * e2v + w3.w * e3v;
        }

        float4 res = *(const float4*)&g_res[(size_t)n * DOUT + c0];
        float4 h;
        h.x = fmaxf(acc.x + elin.x, 0.f) + res.x;
        h.y = fmaxf(acc.y + elin.y, 0.f) + res.y;
        h.z = fmaxf(acc.z + elin.z, 0.f) + res.z;
        h.w = fmaxf(acc.w + elin.w, 0.f) + res.w;
        *(float4*)&g_h[(size_t)n * DOUT + c0] = h;

        atomicAdd(&s_sum[c0 + 0], h.x);
        atomicAdd(&s_sum[c0 + 1], h.y);
        atomicAdd(&s_sum[c0 + 2], h.z);
        atomicAdd(&s_sum[c0 + 3], h.w);
        atomicAdd(&s_sq[c0 + 0], h.x * h.x);
        atomicAdd(&s_sq[c0 + 1], h.y * h.y);
        atomicAdd(&s_sq[c0 + 2], h.z * h.z);
        atomicAdd(&s_sq[c0 + 3], h.w * h.w);
    }

    __syncthreads();
    if (tid < 128) {
        atomicAdd(&g_sum[tid],   s_sum[tid]);
        atomicAdd(&g_sumsq[tid], s_sq[tid]);
    }
}

// ---------------- K4: finalize BN stats (consumes + resets accumulators) -----
__global__ void k4_stats(const float* __restrict__ gamma,
                         const float* __restrict__ beta, int N)
{
    int c = threadIdx.x;
    float invN = 1.f / (float)N;
    float s  = g_sum[c];
    float s2 = g_sumsq[c];
    g_sum[c] = 0.f;
    g_sumsq[c] = 0.f;
    float mean = s * invN;
    float var  = s2 * invN - mean * mean;
    float rstd = rsqrtf(var + BN_EPS);
    float sc   = gamma[c] * rstd;
    g_scale[c] = sc;
    g_shift[c] = beta[c] - mean * sc;
}

// ---------------- K5: normalize ----------------------------------------------
__global__ __launch_bounds__(256)
void k5_norm(float* __restrict__ out, int total4)
{
    int idx = blockIdx.x * blockDim.x + threadIdx.x;
    if (idx >= total4) return;
    int c4 = (idx & (DOUT / 4 - 1)) * 4;
    float4 h  = *(const float4*)&g_h[idx * 4];
    float4 sc = *(const float4*)&g_scale[c4];
    float4 sh = *(const float4*)&g_shift[c4];
    float4 o;
    o.x = h.x * sc.x + sh.x;
    o.y = h.y * sc.y + sh.y;
    o.z = h.z * sc.z + sh.z;
    o.w = h.w * sc.w + sh.w;
    ((float4*)out)[idx] = o;
}

// ---------------- launch ------------------------------------------------------
extern "C" void kernel_launch(void* const* d_in, const int* in_sizes, int n_in,
                              void* d_out, int out_size)
{
    const float* feats = (const float*)d_in[0];
    const void*  ei    = d_in[1];
    const float* eattr = (const float*)d_in[2];
    const float* Wrel  = (const float*)d_in[3];
    const float* brel  = (const float*)d_in[4];
    const float* We    = (const float*)d_in[5];
    const float* be    = (const float*)d_in[6];
    const float* Wres  = (const float*)d_in[7];
    const float* bres  = (const float*)d_in[8];
    const float* gamma = (const float*)d_in[9];
    const float* beta  = (const float*)d_in[10];

    const int N = in_sizes[0] / DIN;
    const int E = in_sizes[2] / EDIM;
    const int nb = (N + SCAN_BLK - 1) / SCAN_BLK;

    static int smem_set = 0;
    if (!smem_set) {
        cudaFuncSetAttribute(k1_gemm_tf32,
                             cudaFuncAttributeMaxDynamicSharedMemorySize, K1_SMEM);
        smem_set = 1;
    }

    k_hist<<<(E + 255) / 256, 256>>>(ei, E);
    k_scan1<<<nb, SCAN_BLK>>>(N);
    k_scan3m<<<nb, SCAN_BLK>>>(nb, N);
    k_place<<<(E + 255) / 256, 256>>>(ei, eattr, E);
    dim3 g1((N + 127) / 128, 4);
    k1_gemm_tf32<<<g1, 256, K1_SMEM>>>(feats, Wrel, brel, Wres, bres, N);
    k_pull<<<(N + 7) / 8, 256>>>(We, be, N);
    k4_stats<<<1, 128>>>(gamma, beta, N);
    int total4 = N * DOUT / 4;
    k5_norm<<<(total4 + 255) / 256, 256>>>((float*)d_out, total4);
}

// round 14
// speedup vs baseline: 1.0135x; 1.0135x over previous
#include <cuda_runtime.h>
#include <cuda_fp16.h>
#include <cstdint>

#define DIN  128
#define DOUT 128
#define EDIM 16
#define MAXN 50176
#define MAXE 819200
#define BN_EPS 1e-5f
#define SCAN_BLK 512
#define NWARPS (SCAN_BLK / 32)   // 16
#define MAXB1 128                // >= ceil(MAXN/SCAN_BLK) = 98

// ---------------- device scratch (static; zero-initialized at load) ---------
// Invariant: g_cnt, g_sum, g_sumsq, g_ea are ZERO at the start of every
// kernel_launch run (statics zero-init; each run re-zeroes after use).
__device__ __half g_x [MAXN * DOUT];   // feats @ W_rel^T + b_rel  (fp16!)
__device__ float g_res[MAXN * DOUT];   // relu(feats @ W_res^T + b_res)
__device__ float g_h  [MAXN * DOUT];   // pre-BN activations
__device__ float g_ea [MAXN * EDIM];   // scatter-add of edge_attr per dst
__device__ int   g_cnt[MAXN];          // per-dst degree (histogram)
__device__ int   g_off[MAXN + 1];      // CSR offsets
__device__ int   g_cur[MAXN];          // placement cursors
__device__ int   g_csr_src[MAXE];      // src node per CSR slot
__device__ int   g_bsum[MAXB1];        // scan phase-1 block sums
__device__ float g_sum  [DOUT];
__device__ float g_sumsq[DOUT];
__device__ float g_scale[DOUT];
__device__ float g_shift[DOUT];
__device__ int   g_is64;               // edge_index dtype flag

__device__ __forceinline__ void red_add_v4(float* p, float4 v) {
    asm volatile("red.global.add.v4.f32 [%0], {%1,%2,%3,%4};"
                 :: "l"(p), "f"(v.x), "f"(v.y), "f"(v.z), "f"(v.w)
                 : "memory");
}

__device__ __forceinline__ uint32_t cvt_tf32(float a) {
    uint32_t r;
    asm("cvt.rna.tf32.f32 %0, %1;" : "=r"(r) : "f"(a));
    return r;
}

__device__ __forceinline__ void mma_tf32(float* d, const uint32_t* a, const uint32_t* b) {
    asm volatile(
        "mma.sync.aligned.m16n8k8.row.col.f32.tf32.tf32.f32 "
        "{%0,%1,%2,%3}, {%4,%5,%6,%7}, {%8,%9}, {%0,%1,%2,%3};"
        : "+f"(d[0]), "+f"(d[1]), "+f"(d[2]), "+f"(d[3])
        : "r"(a[0]), "r"(a[1]), "r"(a[2]), "r"(a[3]), "r"(b[0]), "r"(b[1]));
}

// ---------------- K_hist: per-block dtype detect + histogram over dst --------
__global__ __launch_bounds__(256)
void k_hist(const void* __restrict__ ei_raw, int E)
{
    __shared__ int blk_nz;
    const unsigned int* w = (const unsigned int*)ei_raw;
    if (threadIdx.x == 0) blk_nz = 0;
    __syncthreads();
    if (w[2 * threadIdx.x + 1] != 0u) atomicOr(&blk_nz, 1);
    __syncthreads();
    const int is64 = blk_nz ? 0 : 1;
    if (blockIdx.x == 0 && threadIdx.x == 0) g_is64 = is64;

    int e = blockIdx.x * blockDim.x + threadIdx.x;
    if (e >= E) return;
    int d = is64 ? (int)((const long long*)ei_raw)[E + e]
                 : ((const int*)ei_raw)[E + e];
    atomicAdd(&g_cnt[d], 1);
}

// ---------------- K_scan1: per-block sums -------------------------------------
__global__ __launch_bounds__(SCAN_BLK)
void k_scan1(int N)
{
    __shared__ int wsum[NWARPS];
    int i = blockIdx.x * SCAN_BLK + threadIdx.x;
    int wid = threadIdx.x >> 5, lane = threadIdx.x & 31;
    int v = (i < N) ? g_cnt[i] : 0;
    #pragma unroll
    for (int o = 16; o > 0; o >>= 1) v += __shfl_down_sync(0xffffffffu, v, o);
    if (lane == 0) wsum[wid] = v;
    __syncthreads();
    if (wid == 0) {
        int s = (lane < NWARPS) ? wsum[lane] : 0;
        #pragma unroll
        for (int o = 16; o > 0; o >>= 1) s += __shfl_down_sync(0xffffffffu, s, o);
        if (lane == 0) g_bsum[blockIdx.x] = s;
    }
}

// ---------------- K_scan3m: block-local scan + inline cross-block offset -----
__global__ __launch_bounds__(SCAN_BLK)
void k_scan3m(int nb, int N)
{
    __shared__ int wsum[NWARPS];
    __shared__ int s_boff, s_total;
    int i = blockIdx.x * SCAN_BLK + threadIdx.x;
    int wid = threadIdx.x >> 5, lane = threadIdx.x & 31;

    if (wid == 0) {
        int pre = 0, tot = 0;
        for (int b = lane; b < nb; b += 32) {
            int s = g_bsum[b];
            tot += s;
            if (b < (int)blockIdx.x) pre += s;
        }
        #pragma unroll
        for (int o = 16; o > 0; o >>= 1) {
            pre += __shfl_down_sync(0xffffffffu, pre, o);
            tot += __shfl_down_sync(0xffffffffu, tot, o);
        }
        if (lane == 0) { s_boff = pre; s_total = tot; }
    }

    int v = (i < N) ? g_cnt[i] : 0;
    int x = v;
    #pragma unroll
    for (int o = 1; o < 32; o <<= 1) {
        int y = __shfl_up_sync(0xffffffffu, x, o);
        if (lane >= o) x += y;
    }
    if (lane == 31) wsum[wid] = x;
    __syncthreads();
    if (wid == 0) {
        int s = (lane < NWARPS) ? wsum[lane] : 0;
        #pragma unroll
        for (int o = 1; o < 32; o <<= 1) {
            int y = __shfl_up_sync(0xffffffffu, s, o);
            if (lane >= o) s += y;
        }
        if (lane < NWARPS) wsum[lane] = s;
    }
    __syncthreads();
    int woff = (wid > 0) ? wsum[wid - 1] : 0;
    int excl = x - v + woff + s_boff;
    if (i < N) {
        g_off[i] = excl;
        g_cur[i] = excl;
        g_cnt[i] = 0;                      // restore zero-invariant
    }
    if (blockIdx.x == nb - 1 && threadIdx.x == 0) g_off[N] = s_total;
}

// ---------------- K_place: CSR placement + scatter edge_attr sums ------------
__global__ __launch_bounds__(256)
void k_place(const void* __restrict__ ei_raw, const float* __restrict__ eattr, int E)
{
    int e = blockIdx.x * blockDim.x + threadIdx.x;
    if (e >= E) return;
    int s, d;
    if (g_is64) {
        const long long* p = (const long long*)ei_raw;
        s = (int)p[e]; d = (int)p[E + e];
    } else {
        const int* p = (const int*)ei_raw;
        s = p[e]; d = p[E + e];
    }
    int pos = atomicAdd(&g_cur[d], 1);
    g_csr_src[pos] = s;

    const float4* a4 = (const float4*)&eattr[(size_t)e * EDIM];
    float* dst = &g_ea[(size_t)d * EDIM];
    red_add_v4(dst + 0,  a4[0]);
    red_add_v4(dst + 4,  a4[1]);
    red_add_v4(dst + 8,  a4[2]);
    red_add_v4(dst + 12, a4[3]);
}

// ---------------- K1: tf32 tensor-core node GEMMs (R9 layout; g_x fp16) ------
#define K1_KT       64
#define K1_PITCH    68
#define K1_AS_FL    (128 * K1_PITCH)        // 8704 floats
#define K1_BF_FL    (8 * 8 * 32 * 4)        // 8192 floats
#define K1_SMEM     ((K1_AS_FL + K1_BF_FL) * 4)   // 67584 bytes

__global__ __launch_bounds__(256)
void k1_gemm_tf32(const float* __restrict__ feats,
                  const float* __restrict__ Wrel, const float* __restrict__ brel,
                  const float* __restrict__ Wres, const float* __restrict__ bres,
                  int N)
{
    extern __shared__ float smem[];
    float* As = smem;              // [128][68] fp32
    float* Bf = smem + K1_AS_FL;   // frag-major B hi/lo

    const int tid   = threadIdx.x;
    const int m0    = blockIdx.x * 128;
    const int mat   = blockIdx.y >> 1;
    const int nhalf = blockIdx.y & 1;

    const float* Wsel = (mat == 0) ? Wrel : Wres;
    const float* bsel = (mat == 0) ? brel : bres;
    const int nbase = nhalf * 64;

    const int warp = tid >> 5, lane = tid & 31;
    const int g = lane >> 2, tig = lane & 3;
    const int mwarp = warp >> 1;
    const int nwarp = warp & 1;
    const int am0 = mwarp * 32;

    float d[2][4][4];
    #pragma unroll
    for (int mi = 0; mi < 2; mi++)
        #pragma unroll
        for (int ns = 0; ns < 4; ns++)
            #pragma unroll
            for (int q = 0; q < 4; q++) d[mi][ns][q] = 0.f;

    for (int kt = 0; kt < DIN / K1_KT; kt++) {
        const int koff = kt * K1_KT;
        __syncthreads();
        for (int idx = tid; idx < 128 * 16; idx += 256) {
            int row = idx >> 4, c4 = idx & 15;
            int node = m0 + row;
            float4 v = (node < N)
                ? *(const float4*)&feats[(size_t)node * DIN + koff + c4 * 4]
                : make_float4(0.f, 0.f, 0.f, 0.f);
            *(float4*)&As[row * K1_PITCH + c4 * 4] = v;
        }
        for (int idx = tid; idx < 8 * 8 * 32; idx += 256) {
            int ks = idx >> 8;
            int ns = (idx >> 5) & 7;
            int ln = idx & 31;
            int gg = ln >> 2, tg = ln & 3;
            int nrow = nbase + ns * 8 + gg;
            const float* wr = &Wsel[(size_t)nrow * DIN + koff + ks * 8 + tg];
            float w0 = wr[0], w1 = wr[4];
            uint32_t h0 = cvt_tf32(w0);
            uint32_t h1 = cvt_tf32(w1);
            uint32_t l0 = cvt_tf32(w0 - __uint_as_float(h0));
            uint32_t l1 = cvt_tf32(w1 - __uint_as_float(h1));
            *(float4*)&Bf[(size_t)idx * 4] =
                make_float4(__uint_as_float(h0), __uint_as_float(h1),
                            __uint_as_float(l0), __uint_as_float(l1));
        }
        __syncthreads();

        #pragma unroll
        for (int ks = 0; ks < K1_KT / 8; ks++) {
            const int k0 = ks * 8;
            float af[8];
            #pragma unroll
            for (int mi = 0; mi < 2; mi++) {
                int r0 = am0 + mi * 16 + g;
                af[mi*4+0] = As[r0 * K1_PITCH + k0 + tig];
                af[mi*4+1] = As[(r0 + 8) * K1_PITCH + k0 + tig];
                af[mi*4+2] = As[r0 * K1_PITCH + k0 + tig + 4];
                af[mi*4+3] = As[(r0 + 8) * K1_PITCH + k0 + tig + 4];
            }
            uint32_t ah[8], al[8];
            #pragma unroll
            for (int q = 0; q < 8; q++) {
                ah[q] = cvt_tf32(af[q]);
                al[q] = cvt_tf32(af[q] - __uint_as_float(ah[q]));
            }
            #pragma unroll
            for (int nsl = 0; nsl < 4; nsl++) {
                const int nsg = nwarp * 4 + nsl;
                float4 b = *(const float4*)&Bf[((ks * 8 + nsg) * 32 + lane) * 4];
                uint32_t bh[2] = {__float_as_uint(b.x), __float_as_uint(b.y)};
                uint32_t bl[2] = {__float_as_uint(b.z), __float_as_uint(b.w)};
                #pragma unroll
                for (int mi = 0; mi < 2; mi++) {
                    mma_tf32(d[mi][nsl], ah + 4*mi, bh);
                    mma_tf32(d[mi][nsl], al + 4*mi, bh);
                    mma_tf32(d[mi][nsl], ah + 4*mi, bl);
                }
            }
        }
    }

    // epilogue: bias; mat 0 -> fp16 g_x, mat 1 -> relu fp32 g_res
    #pragma unroll
    for (int mi = 0; mi < 2; mi++) {
        const int rA = m0 + am0 + mi * 16 + g;
        #pragma unroll
        for (int nsl = 0; nsl < 4; nsl++) {
            const int col = nbase + (nwarp * 4 + nsl) * 8 + tig * 2;
            float b0 = bsel[col], b1 = bsel[col + 1];
            float v0 = d[mi][nsl][0] + b0, v1 = d[mi][nsl][1] + b1;
            float v2 = d[mi][nsl][2] + b0, v3 = d[mi][nsl][3] + b1;
            if (mat == 0) {
                if (rA < N)
                    *(__half2*)&g_x[(size_t)rA * DOUT + col] = __floats2half2_rn(v0, v1);
                if (rA + 8 < N)
                    *(__half2*)&g_x[(size_t)(rA + 8) * DOUT + col] = __floats2half2_rn(v2, v3);
            } else {
                v0 = fmaxf(v0, 0.f); v1 = fmaxf(v1, 0.f);
                v2 = fmaxf(v2, 0.f); v3 = fmaxf(v3, 0.f);
                if (rA < N)
                    *(float2*)&g_res[(size_t)rA * DOUT + col] = make_float2(v0, v1);
                if (rA + 8 < N)
                    *(float2*)&g_res[(size_t)(rA + 8) * DOUT + col] = make_float2(v2, v3);
            }
        }
    }
}

// ---------------- K_pull: fp16 gather + combine + BN partials ----------------
__global__ __launch_bounds__(256)
void k_pull(const float* __restrict__ We, const float* __restrict__ be, int N)
{
    __shared__ float s_sum[128];
    __shared__ float s_sq[128];
    int tid = threadIdx.x;
    if (tid < 128) { s_sum[tid] = 0.f; s_sq[tid] = 0.f; }
    __syncthreads();

    int warp = tid >> 5, lane = tid & 31;
    int n = blockIdx.x * 8 + warp;

    if (n < N) {
        const int j0 = g_off[n], j1 = g_off[n + 1];
        const int c0 = lane * 4;

        float4 acc = make_float4(0.f, 0.f, 0.f, 0.f);

        for (int base = j0; base < j1; base += 32) {
            int myidx = g_csr_src[base + lane];   // coalesced; overread bounded by MAXE
            int cnt = j1 - base; if (cnt > 32) cnt = 32;
            int t = 0;
            for (; t + 3 < cnt; t += 4) {
                int s0 = __shfl_sync(0xffffffffu, myidx, t);
                int s1 = __shfl_sync(0xffffffffu, myidx, t + 1);
                int s2 = __shfl_sync(0xffffffffu, myidx, t + 2);
                int s3 = __shfl_sync(0xffffffffu, myidx, t + 3);
                uint2 r0 = *(const uint2*)&g_x[(size_t)s0 * DOUT + c0];
                uint2 r1 = *(const uint2*)&g_x[(size_t)s1 * DOUT + c0];
                uint2 r2 = *(const uint2*)&g_x[(size_t)s2 * DOUT + c0];
                uint2 r3 = *(const uint2*)&g_x[(size_t)s3 * DOUT + c0];
                float2 a0 = __half22float2(*(__half2*)&r0.x);
                float2 b0 = __half22float2(*(__half2*)&r0.y);
                float2 a1 = __half22float2(*(__half2*)&r1.x);
                float2 b1 = __half22float2(*(__half2*)&r1.y);
                float2 a2 = __half22float2(*(__half2*)&r2.x);
                float2 b2 = __half22float2(*(__half2*)&r2.y);
                float2 a3 = __half22float2(*(__half2*)&r3.x);
                float2 b3 = __half22float2(*(__half2*)&r3.y);
                acc.x += (a0.x + a1.x) + (a2.x + a3.x);
                acc.y += (a0.y + a1.y) + (a2.y + a3.y);
                acc.z += (b0.x + b1.x) + (b2.x + b3.x);
                acc.w += (b0.y + b1.y) + (b2.y + b3.y);
            }
            for (; t < cnt; t++) {
                int s0 = __shfl_sync(0xffffffffu, myidx, t);
                uint2 r0 = *(const uint2*)&g_x[(size_t)s0 * DOUT + c0];
                float2 a0 = __half22float2(*(__half2*)&r0.x);
                float2 b0 = __half22float2(*(__half2*)&r0.y);
                acc.x += a0.x; acc.y += a0.y; acc.z += b0.x; acc.w += b0.y;
            }
        }

        // per-dst summed edge_attr -> broadcast; then reset for next run
        float ea = 0.f;
        if (lane < EDIM) {
            ea = g_ea[(size_t)n * EDIM + lane];
            g_ea[(size_t)n * EDIM + lane] = 0.f;
        }
        float eav[EDIM];
        #pragma unroll
        for (int q = 0; q < EDIM; q++) eav[q] = __shfl_sync(0xffffffffu, ea, q);

        const float deg = (float)(j1 - j0);
        float4 b = *(const float4*)&be[c0];
        float4 elin = make_float4(b.x * deg, b.y * deg, b.z * deg, b.w * deg);

        const float4* W4 = (const float4*)We;
        #pragma unroll
        for (int q4 = 0; q4 < 4; q4++) {
            float4 w0 = W4[(c0 + 0) * 4 + q4];
            float4 w1 = W4[(c0 + 1) * 4 + q4];
            float4 w2 = W4[(c0 + 2) * 4 + q4];
            float4 w3 = W4[(c0 + 3) * 4 + q4];
            float e0v = eav[q4 * 4 + 0], e1v = eav[q4 * 4 + 1];
            float e2v = eav[q4 * 4 + 2], e3v = eav[q4 * 4 + 3];
            elin.x += w0.x * e0v + w0.y * e1v + w0.z * e2v + w0.w * e3v;
            elin.y += w1.x * e0v + w1.y * e1v + w1.z * e2v + w1.w * e3v;
            elin.z += w2.x * e0v + w2.y * e1v + w2.z * e2v + w2.w * e3v;
            elin.w += w3.x * e0v + w3.y * e1v + w3.z * e2v + w3.w * e3v;
        }

        float4 res = *(const float4*)&g_res[(size_t)n * DOUT + c0];
        float4 h;
        h.x = fmaxf(acc.x + elin.x, 0.f) + res.x;
        h.y = fmaxf(acc.y + elin.y, 0.f) + res.y;
        h.z = fmaxf(acc.z + elin.z, 0.f) + res.z;
        h.w = fmaxf(acc.w + elin.w, 0.f) + res.w;
        *(float4*)&g_h[(size_t)n * DOUT + c0] = h;

        atomicAdd(&s_sum[c0 + 0], h.x);
        atomicAdd(&s_sum[c0 + 1], h.y);
        atomicAdd(&s_sum[c0 + 2], h.z);
        atomicAdd(&s_sum[c0 + 3], h.w);
        atomicAdd(&s_sq[c0 + 0], h.x * h.x);
        atomicAdd(&s_sq[c0 + 1], h.y * h.y);
        atomicAdd(&s_sq[c0 + 2], h.z * h.z);
        atomicAdd(&s_sq[c0 + 3], h.w * h.w);
    }

    __syncthreads();
    if (tid < 128) {
        atomicAdd(&g_sum[tid],   s_sum[tid]);
        atomicAdd(&g_sumsq[tid], s_sq[tid]);
    }
}

// ---------------- K4: finalize BN stats (consumes + resets accumulators) -----
__global__ void k4_stats(const float* __restrict__ gamma,
                         const float* __restrict__ beta, int N)
{
    int c = threadIdx.x;
    float invN = 1.f / (float)N;
    float s  = g_sum[c];
    float s2 = g_sumsq[c];
    g_sum[c] = 0.f;
    g_sumsq[c] = 0.f;
    float mean = s * invN;
    float var  = s2 * invN - mean * mean;
    float rstd = rsqrtf(var + BN_EPS);
    float sc   = gamma[c] * rstd;
    g_scale[c] = sc;
    g_shift[c] = beta[c] - mean * sc;
}

// ---------------- K5: normalize ----------------------------------------------
__global__ __launch_bounds__(256)
void k5_norm(float* __restrict__ out, int total4)
{
    int idx = blockIdx.x * blockDim.x + threadIdx.x;
    if (idx >= total4) return;
    int c4 = (idx & (DOUT / 4 - 1)) * 4;
    float4 h  = *(const float4*)&g_h[idx * 4];
    float4 sc = *(const float4*)&g_scale[c4];
    float4 sh = *(const float4*)&g_shift[c4];
    float4 o;
    o.x = h.x * sc.x + sh.x;
    o.y = h.y * sc.y + sh.y;
    o.z = h.z * sc.z + sh.z;
    o.w = h.w * sc.w + sh.w;
    ((float4*)out)[idx] = o;
}

// ---------------- launch ------------------------------------------------------
extern "C" void kernel_launch(void* const* d_in, const int* in_sizes, int n_in,
                              void* d_out, int out_size)
{
    const float* feats = (const float*)d_in[0];
    const void*  ei    = d_in[1];
    const float* eattr = (const float*)d_in[2];
    const float* Wrel  = (const float*)d_in[3];
    const float* brel  = (const float*)d_in[4];
    const float* We    = (const float*)d_in[5];
    const float* be    = (const float*)d_in[6];
    const float* Wres  = (const float*)d_in[7];
    const float* bres  = (const float*)d_in[8];
    const float* gamma = (const float*)d_in[9];
    const float* beta  = (const float*)d_in[10];

    const int N = in_sizes[0] / DIN;
    const int E = in_sizes[2] / EDIM;
    const int nb = (N + SCAN_BLK - 1) / SCAN_BLK;

    static int smem_set = 0;
    if (!smem_set) {
        cudaFuncSetAttribute(k1_gemm_tf32,
                             cudaFuncAttributeMaxDynamicSharedMemorySize, K1_SMEM);
        smem_set = 1;
    }

    k_hist<<<(E + 255) / 256, 256>>>(ei, E);
    k_scan1<<<nb, SCAN_BLK>>>(N);
    k_scan3m<<<nb, SCAN_BLK>>>(nb, N);
    k_place<<<(E + 255) / 256, 256>>>(ei, eattr, E);
    dim3 g1((N + 127) / 128, 4);
    k1_gemm_tf32<<<g1, 256, K1_SMEM>>>(feats, Wrel, brel, Wres, bres, N);
    k_pull<<<(N + 7) / 8, 256>>>(We, be, N);
    k4_stats<<<1, 128>>>(gamma, beta, N);
    int total4 = N * DOUT / 4;
    k5_norm<<<(total4 + 255) / 256, 256>>>((float*)d_out, total4);
}